// round 9
// baseline (speedup 1.0000x reference)
#include <cuda_runtime.h>
#include <cuda_bf16.h>
#include <cstdint>

#define IH 400
#define IW 400
#define NPIX 160000
#define F1 128
#define F2 64
#define F3 8

#define PW 416                 // padded image stride / height
#define CH (PW * PW)           // per-channel padded elems

// ---- smem layout (bytes) ----
// OFF_BBUF: staging buffer, reused across phases.
//   phase 1 (layer 1): B1 chunk fragments, 4096 x uint4 = 65536 B at [0,65536)
//   phase 2 (layer 2+): W2 fragments 2048 x uint4 = 32768 B at [0,32768),
//                       h2 staging 4*32*65*4 = 33280 B at [32768,66048)
#define OFF_BBUF 0
#define OFF_H2S  32768
#define OFF_B1S  66048
#define OFF_B2S  66560
#define OFF_B3S  66816
#define OFF_W3S  66848
#define OFF_KOF  68896
#define SMEM_BYTES 69408

// padded input image, zero border: [3][416][416]
__device__ float g_xp[3 * CH];
// Pre-packed weight fragments (uint4 = {bh0,bh1,bl0,bl1} per lane)
__device__ uint4 g_B1f[3 * 4096];          // [chunk][kt][ni][lane]
__device__ uint4 g_W2f[2048];              // [kt][ni2][lane] -- 2048 slots!

// ---------------- helpers ----------------
__device__ __forceinline__ uint32_t cvt2(float hi_val, float lo_val) {
    uint32_t r;
    asm("cvt.rn.bf16x2.f32 %0, %1, %2;" : "=r"(r) : "f"(hi_val), "f"(lo_val));
    return r;
}
// split (v0,v1) into hi bf16x2 + residual-lo bf16x2 (low half = v0)
__device__ __forceinline__ void split2(float v0, float v1, uint32_t& h, uint32_t& l) {
    h = cvt2(v1, v0);
    float f0 = __uint_as_float(h << 16);
    float f1 = __uint_as_float(h & 0xFFFF0000u);
    l = cvt2(v1 - f1, v0 - f0);
}
__device__ __forceinline__ float lrelu(float t) { return t > 0.f ? t : 0.01f * t; }

#define MMA(d, a, b0_, b1_) \
    asm("mma.sync.aligned.m16n8k16.row.col.f32.bf16.bf16.f32 " \
        "{%0,%1,%2,%3},{%4,%5,%6,%7},{%8,%9},{%0,%1,%2,%3};" \
        : "+f"((d).x), "+f"((d).y), "+f"((d).z), "+f"((d).w) \
        : "r"((a)[0]), "r"((a)[1]), "r"((a)[2]), "r"((a)[3]), "r"(b0_), "r"(b1_))

// ---------------------------------------------------------------------------
// Prep 1: pad x into g_xp (zero border, +5 offset)
// ---------------------------------------------------------------------------
__global__ void pad_k(const float* __restrict__ x) {
    int i = blockIdx.x * 256 + threadIdx.x;
    if (i >= 3 * CH) return;
    int c = i / CH, rem = i - c * CH;
    int gy = rem / PW, gx = rem - gy * PW;
    float v = 0.f;
    int sy = gy - 5, sx = gx - 5;
    if ((unsigned)sy < (unsigned)IH && (unsigned)sx < (unsigned)IW)
        v = x[(c * IH + sy) * IW + sx];
    g_xp[i] = v;
}

// ---------------------------------------------------------------------------
// Prep 2: pack W1 (363x128) and W2 (128x64) into mma.sync b-fragment layout,
// bf16 hi + residual lo, zero-padded K.
// ---------------------------------------------------------------------------
__global__ void prep_k(const float* __restrict__ W1, const float* __restrict__ W2) {
    int t = blockIdx.x * 256 + threadIdx.x;
    if (t >= 12288 + 2048) return;
    if (t < 12288) {
        int lane = t & 31, ni = (t >> 5) & 15, kt = (t >> 9) & 7, chunk = t >> 12;
        int c = lane & 3, g = lane >> 2;
        int n = ni * 8 + g;
        int k0 = kt * 16 + 2 * c;
        float v00 = 0.f, v01 = 0.f, v10 = 0.f, v11 = 0.f;
        if (k0 + 1 < 121) {
            v00 = W1[(chunk * 121 + k0) * F1 + n];
            v01 = W1[(chunk * 121 + k0 + 1) * F1 + n];
        } else if (k0 < 121) {
            v00 = W1[(chunk * 121 + k0) * F1 + n];
        }
        if (k0 + 9 < 121) {
            v10 = W1[(chunk * 121 + k0 + 8) * F1 + n];
            v11 = W1[(chunk * 121 + k0 + 9) * F1 + n];
        } else if (k0 + 8 < 121) {
            v10 = W1[(chunk * 121 + k0 + 8) * F1 + n];
        }
        uint4 o;
        split2(v00, v01, o.x, o.z);
        split2(v10, v11, o.y, o.w);
        g_B1f[t] = o;
    } else {
        int t2 = t - 12288;
        int lane = t2 & 31, ni2 = (t2 >> 5) & 7, kt = t2 >> 8;
        int c = lane & 3, g = lane >> 2;
        int n = ni2 * 8 + g;
        int k0 = kt * 16 + 2 * c;
        float v00 = W2[k0 * F2 + n];
        float v01 = W2[(k0 + 1) * F2 + n];
        float v10 = W2[(k0 + 8) * F2 + n];
        float v11 = W2[(k0 + 9) * F2 + n];
        uint4 o;
        split2(v00, v01, o.x, o.z);
        split2(v10, v11, o.y, o.w);
        g_W2f[t2] = o;
    }
}

// ---------------------------------------------------------------------------
// Main: CTA = 128 px, 4 warps x 32 px. A fragments built in registers from the
// padded image; B fragments staged per-chunk in smem (shared by all warps) and
// read via conflict-free LDS.128.
// ---------------------------------------------------------------------------
__global__ void __launch_bounds__(128) main_k(const float* __restrict__ b1,
                                              const float* __restrict__ b2,
                                              const float* __restrict__ b3,
                                              const float* __restrict__ W3,
                                              float* __restrict__ out)
{
    extern __shared__ char smem[];
    uint4* sbuf = (uint4*)(smem + OFF_BBUF);
    float* sb1 = (float*)(smem + OFF_B1S);
    float* sb2 = (float*)(smem + OFF_B2S);
    float* sb3 = (float*)(smem + OFF_B3S);
    float* sW3 = (float*)(smem + OFF_W3S);
    int2*  kof = (int2*)(smem + OFF_KOF);

    const int tid = threadIdx.x;
    const int w = tid >> 5;
    const int lane = tid & 31;
    const int c4 = lane & 3, g = lane >> 2;

    if (tid < F1) sb1[tid] = b1[tid];
    if (tid < F2) sb2[tid] = b2[tid];
    if (tid < F3) sb3[tid] = b3[tid];
    for (int i = tid; i < F2 * F3; i += 128) sW3[i] = W3[i];
    if (tid < 64) {                       // k -> padded-image offset table
        int k0 = 2 * tid, k1 = 2 * tid + 1;
        kof[tid] = make_int2((k0 / 11) * PW + (k0 % 11),
                             (k1 / 11) * PW + (k1 % 11));
    }

    // 4 pixel base offsets for this lane: rows g, g+8 in mi=0 / mi=1 tiles
    int pbase[2][2];
#pragma unroll
    for (int mi = 0; mi < 2; mi++)
#pragma unroll
        for (int rr = 0; rr < 2; rr++) {
            int p = blockIdx.x * 128 + w * 32 + mi * 16 + rr * 8 + g;
            int py = p / IW;
            pbase[mi][rr] = py * PW + (p - py * IW);
        }

    float4 d1[2][16];
#pragma unroll
    for (int mi = 0; mi < 2; mi++)
#pragma unroll
        for (int ni = 0; ni < 16; ni++) d1[mi][ni] = make_float4(0.f, 0.f, 0.f, 0.f);

    // ================= layer 1: K = 3 chunks x 128 (121 valid) =============
#pragma unroll 1
    for (int chunk = 0; chunk < 3; chunk++) {
        const float* xc = g_xp + chunk * CH;

        __syncthreads();   // previous chunk's LDS reads done (also covers tables)
        {
            const uint4* src = g_B1f + chunk * 4096;
#pragma unroll
            for (int i = 0; i < 32; i++)
                sbuf[tid + i * 128] = __ldg(src + tid + i * 128);
        }
        __syncthreads();   // staged data visible

#pragma unroll 1
        for (int kt = 0; kt < 8; kt++) {
            uint32_t ah[2][4], al[2][4];
#pragma unroll
            for (int j = 0; j < 2; j++) {
                int2 off = kof[kt * 8 + c4 + 4 * j];
#pragma unroll
                for (int mi = 0; mi < 2; mi++) {
                    float v00 = __ldg(xc + pbase[mi][0] + off.x);
                    float v01 = __ldg(xc + pbase[mi][0] + off.y);
                    float v10 = __ldg(xc + pbase[mi][1] + off.x);
                    float v11 = __ldg(xc + pbase[mi][1] + off.y);
                    split2(v00, v01, ah[mi][2 * j],     al[mi][2 * j]);
                    split2(v10, v11, ah[mi][2 * j + 1], al[mi][2 * j + 1]);
                }
            }
            const uint4* bp = sbuf + (kt * 16) * 32 + lane;
#pragma unroll
            for (int ni = 0; ni < 16; ni++) {
                uint4 bb = bp[ni * 32];
                MMA(d1[0][ni], ah[0], bb.x, bb.y);
                MMA(d1[1][ni], ah[1], bb.x, bb.y);
                MMA(d1[0][ni], ah[0], bb.z, bb.w);
                MMA(d1[1][ni], ah[1], bb.z, bb.w);
                MMA(d1[0][ni], al[0], bb.x, bb.y);
                MMA(d1[1][ni], al[1], bb.x, bb.y);
            }
        }
    }

    // ---- stage ALL 2048 W2 fragments (32KB) into the buffer front ----
    __syncthreads();   // layer-1 LDS reads done
#pragma unroll
    for (int i = 0; i < 16; i++)
        sbuf[tid + i * 128] = __ldg(g_W2f + tid + i * 128);
    __syncthreads();

    // ============ layer 2: bias+leaky+split in regs, mma 128->64 ===========
    float4 d2[2][8];
#pragma unroll
    for (int mi = 0; mi < 2; mi++)
#pragma unroll
        for (int ni = 0; ni < 8; ni++) d2[mi][ni] = make_float4(0.f, 0.f, 0.f, 0.f);

#pragma unroll
    for (int kt = 0; kt < 8; kt++) {
        uint32_t ah[2][4], al[2][4];
#pragma unroll
        for (int half = 0; half < 2; half++) {
            int ni = 2 * kt + half;
            float2 bb = *(const float2*)&sb1[8 * ni + 2 * c4];
#pragma unroll
            for (int mi = 0; mi < 2; mi++) {
                float4 D = d1[mi][ni];
                float v0 = lrelu(D.x + bb.x);
                float v1 = lrelu(D.y + bb.y);
                float v2 = lrelu(D.z + bb.x);
                float v3 = lrelu(D.w + bb.y);
                split2(v0, v1, ah[mi][half * 2], al[mi][half * 2]);
                split2(v2, v3, ah[mi][half * 2 + 1], al[mi][half * 2 + 1]);
            }
        }
        const uint4* wp = sbuf + (kt * 8) * 32 + lane;
#pragma unroll
        for (int ni = 0; ni < 8; ni++) {
            uint4 ww = wp[ni * 32];
            MMA(d2[0][ni], ah[0], ww.x, ww.y);
            MMA(d2[1][ni], ah[1], ww.x, ww.y);
            MMA(d2[0][ni], ah[0], ww.z, ww.w);
            MMA(d2[1][ni], ah[1], ww.z, ww.w);
            MMA(d2[0][ni], al[0], ww.x, ww.y);
            MMA(d2[1][ni], al[1], ww.x, ww.y);
        }
    }

    // ============ h2 -> padded smem, per-pixel 64->8 + normalize ===========
    float* h2s = (float*)(smem + OFF_H2S) + w * (32 * 65);
#pragma unroll
    for (int ni = 0; ni < 8; ni++) {
        float2 bb = *(const float2*)&sb2[8 * ni + 2 * c4];
        int ch = 8 * ni + 2 * c4;
#pragma unroll
        for (int mi = 0; mi < 2; mi++) {
            float4 D = d2[mi][ni];
            int r0 = 16 * mi + g;
            h2s[r0 * 65 + ch]           = lrelu(D.x + bb.x);
            h2s[r0 * 65 + ch + 1]       = lrelu(D.y + bb.y);
            h2s[(r0 + 8) * 65 + ch]     = lrelu(D.z + bb.x);
            h2s[(r0 + 8) * 65 + ch + 1] = lrelu(D.w + bb.y);
        }
    }
    __syncwarp();

    const float* myrow = h2s + lane * 65;
    float v[F3];
#pragma unroll
    for (int e = 0; e < F3; e++) v[e] = sb3[e];
#pragma unroll 8
    for (int k = 0; k < F2; k++) {
        float hk = myrow[k];
        const float4* wr = (const float4*)&sW3[k * F3];
        float4 w0 = wr[0], w1 = wr[1];
        v[0] += hk * w0.x; v[1] += hk * w0.y; v[2] += hk * w0.z; v[3] += hk * w0.w;
        v[4] += hk * w1.x; v[5] += hk * w1.y; v[6] += hk * w1.z; v[7] += hk * w1.w;
    }
    float ss = 0.f;
#pragma unroll
    for (int e = 0; e < F3; e++) ss += v[e] * v[e];
    float inv = 1.0f / fmaxf(sqrtf(ss), 1e-12f);

    const int p = blockIdx.x * 128 + w * 32 + lane;
    float4* o = (float4*)(out + (size_t)p * F3);
    float4 o0, o1;
    o0.x = v[0] * inv; o0.y = v[1] * inv; o0.z = v[2] * inv; o0.w = v[3] * inv;
    o1.x = v[4] * inv; o1.y = v[5] * inv; o1.z = v[6] * inv; o1.w = v[7] * inv;
    o[0] = o0; o[1] = o1;
}

// ---------------------------------------------------------------------------
extern "C" void kernel_launch(void* const* d_in, const int* in_sizes, int n_in,
                              void* d_out, int out_size)
{
    const float* x  = (const float*)d_in[0];
    const float* W1 = (const float*)d_in[1];
    const float* b1 = (const float*)d_in[2];
    const float* W2 = (const float*)d_in[3];
    const float* b2 = (const float*)d_in[4];
    const float* W3 = (const float*)d_in[5];
    const float* b3 = (const float*)d_in[6];
    float* out = (float*)d_out;

    pad_k<<<(3 * CH + 255) / 256, 256>>>(x);
    prep_k<<<(12288 + 2048 + 255) / 256, 256>>>(W1, W2);

    cudaFuncSetAttribute(main_k, cudaFuncAttributeMaxDynamicSharedMemorySize,
                         SMEM_BYTES);
    main_k<<<NPIX / 128, 128, SMEM_BYTES>>>(b1, b2, b3, W3, out);
}

// round 10
// speedup vs baseline: 1.0918x; 1.0918x over previous
#include <cuda_runtime.h>
#include <cuda_bf16.h>
#include <cstdint>

#define IH 400
#define IW 400
#define NPIX 160000
#define F1 128
#define F2 64
#define F3 8

#define PW 416                 // padded image stride / height
#define CH (PW * PW)           // per-channel padded elems

// smem: h2 staging + small tables (R6 layout)
#define OFF_H2S 0              // 4 warps x 32 px x 65 f32 = 33280 B
#define OFF_B1S 33280
#define OFF_B2S 33792
#define OFF_B3S 34048
#define OFF_W3S 34080
#define OFF_KOF 36128          // 64 x int2 = 512 B
#define SMEM_BYTES 36640

// padded input image, hi/lo bf16 packed per pixel: (hi<<16)|lo, zero border
__device__ uint32_t g_xhl[3 * CH];
// Pre-packed weight fragments (uint4 = {bh0,bh1,bl0,bl1} per lane)
__device__ uint4 g_B1f[3 * 4096];          // [chunk][kt][ni][lane]
__device__ uint4 g_W2f[2048];              // [kt][ni2][lane]

// ---------------- helpers ----------------
__device__ __forceinline__ uint32_t cvt2(float hi_val, float lo_val) {
    uint32_t r;
    asm("cvt.rn.bf16x2.f32 %0, %1, %2;" : "=r"(r) : "f"(hi_val), "f"(lo_val));
    return r;
}
// split (v0,v1) into hi bf16x2 + residual-lo bf16x2 (low half = v0)
__device__ __forceinline__ void split2(float v0, float v1, uint32_t& h, uint32_t& l) {
    h = cvt2(v1, v0);
    float f0 = __uint_as_float(h << 16);
    float f1 = __uint_as_float(h & 0xFFFF0000u);
    l = cvt2(v1 - f1, v0 - f0);
}
__device__ __forceinline__ uint32_t prmt(uint32_t a, uint32_t b, uint32_t s) {
    uint32_t r;
    asm("prmt.b32 %0, %1, %2, %3;" : "=r"(r) : "r"(a), "r"(b), "r"(s));
    return r;
}
__device__ __forceinline__ float lrelu(float t) { return t > 0.f ? t : 0.01f * t; }

#define MMA(d, a, b0_, b1_) \
    asm("mma.sync.aligned.m16n8k16.row.col.f32.bf16.bf16.f32 " \
        "{%0,%1,%2,%3},{%4,%5,%6,%7},{%8,%9},{%0,%1,%2,%3};" \
        : "+f"((d).x), "+f"((d).y), "+f"((d).z), "+f"((d).w) \
        : "r"((a)[0]), "r"((a)[1]), "r"((a)[2]), "r"((a)[3]), "r"(b0_), "r"(b1_))

// ---------------------------------------------------------------------------
// Prep 1: pad x into g_xhl (zero border, +5 offset), packed bf16 hi/lo
// ---------------------------------------------------------------------------
__global__ void pad_k(const float* __restrict__ x) {
    int i = blockIdx.x * 256 + threadIdx.x;
    if (i >= 3 * CH) return;
    int c = i / CH, rem = i - c * CH;
    int gy = rem / PW, gx = rem - gy * PW;
    uint32_t word = 0;
    int sy = gy - 5, sx = gx - 5;
    if ((unsigned)sy < (unsigned)IH && (unsigned)sx < (unsigned)IW) {
        float v = x[(c * IH + sy) * IW + sx];
        uint32_t hl;
        asm("cvt.rn.bf16x2.f32 %0, %1, %2;" : "=r"(hl) : "f"(0.f), "f"(v));
        float hf = __uint_as_float(hl << 16);     // hi as f32
        uint32_t lo;
        asm("cvt.rn.bf16x2.f32 %0, %1, %2;" : "=r"(lo) : "f"(0.f), "f"(v - hf));
        word = (hl << 16) | (lo & 0xFFFFu);
    }
    g_xhl[i] = word;
}

// ---------------------------------------------------------------------------
// Prep 2: pack W1 (363x128) and W2 (128x64) into mma.sync b-fragment layout,
// bf16 hi + residual lo, zero-padded K.
// ---------------------------------------------------------------------------
__global__ void prep_k(const float* __restrict__ W1, const float* __restrict__ W2) {
    int t = blockIdx.x * 256 + threadIdx.x;
    if (t >= 12288 + 2048) return;
    if (t < 12288) {
        int lane = t & 31, ni = (t >> 5) & 15, kt = (t >> 9) & 7, chunk = t >> 12;
        int c = lane & 3, g = lane >> 2;
        int n = ni * 8 + g;
        int k0 = kt * 16 + 2 * c;
        float v00 = 0.f, v01 = 0.f, v10 = 0.f, v11 = 0.f;
        if (k0 + 1 < 121) {
            v00 = W1[(chunk * 121 + k0) * F1 + n];
            v01 = W1[(chunk * 121 + k0 + 1) * F1 + n];
        } else if (k0 < 121) {
            v00 = W1[(chunk * 121 + k0) * F1 + n];
        }
        if (k0 + 9 < 121) {
            v10 = W1[(chunk * 121 + k0 + 8) * F1 + n];
            v11 = W1[(chunk * 121 + k0 + 9) * F1 + n];
        } else if (k0 + 8 < 121) {
            v10 = W1[(chunk * 121 + k0 + 8) * F1 + n];
        }
        uint4 o;
        split2(v00, v01, o.x, o.z);
        split2(v10, v11, o.y, o.w);
        g_B1f[t] = o;
    } else {
        int t2 = t - 12288;
        int lane = t2 & 31, ni2 = (t2 >> 5) & 7, kt = t2 >> 8;
        int c = lane & 3, g = lane >> 2;
        int n = ni2 * 8 + g;
        int k0 = kt * 16 + 2 * c;
        float v00 = W2[k0 * F2 + n];
        float v01 = W2[(k0 + 1) * F2 + n];
        float v10 = W2[(k0 + 8) * F2 + n];
        float v11 = W2[(k0 + 9) * F2 + n];
        uint4 o;
        split2(v00, v01, o.x, o.z);
        split2(v10, v11, o.y, o.w);
        g_W2f[t2] = o;
    }
}

// ---------------------------------------------------------------------------
// Main: CTA = 128 px, 4 warps x 32 px. A fragments assembled in registers from
// the pre-split packed image with PRMT (no converts); B fragments via LDG
// (L2/L1-resident). No per-chunk barriers.
// ---------------------------------------------------------------------------
__global__ void __launch_bounds__(128) main_k(const float* __restrict__ b1,
                                              const float* __restrict__ b2,
                                              const float* __restrict__ b3,
                                              const float* __restrict__ W3,
                                              float* __restrict__ out)
{
    extern __shared__ char smem[];
    float* sb1 = (float*)(smem + OFF_B1S);
    float* sb2 = (float*)(smem + OFF_B2S);
    float* sb3 = (float*)(smem + OFF_B3S);
    float* sW3 = (float*)(smem + OFF_W3S);
    int2*  kof = (int2*)(smem + OFF_KOF);

    const int tid = threadIdx.x;
    const int w = tid >> 5;
    const int lane = tid & 31;
    const int c4 = lane & 3, g = lane >> 2;

    if (tid < F1) sb1[tid] = b1[tid];
    if (tid < F2) sb2[tid] = b2[tid];
    if (tid < F3) sb3[tid] = b3[tid];
    for (int i = tid; i < F2 * F3; i += 128) sW3[i] = W3[i];
    if (tid < 64) {                       // k -> padded-image offset table
        int k0 = 2 * tid, k1 = 2 * tid + 1;
        kof[tid] = make_int2((k0 / 11) * PW + (k0 % 11),
                             (k1 / 11) * PW + (k1 % 11));
    }
    __syncthreads();   // only block-wide sync

    // 4 pixel base offsets for this lane: rows g, g+8 in mi=0 / mi=1 tiles
    int pbase[2][2];
#pragma unroll
    for (int mi = 0; mi < 2; mi++)
#pragma unroll
        for (int rr = 0; rr < 2; rr++) {
            int p = blockIdx.x * 128 + w * 32 + mi * 16 + rr * 8 + g;
            int py = p / IW;
            pbase[mi][rr] = py * PW + (p - py * IW);
        }

    float4 d1[2][16];
#pragma unroll
    for (int mi = 0; mi < 2; mi++)
#pragma unroll
        for (int ni = 0; ni < 16; ni++) d1[mi][ni] = make_float4(0.f, 0.f, 0.f, 0.f);

    // ================= layer 1: K = 3 chunks x 128 (121 valid) =============
#pragma unroll 1
    for (int chunk = 0; chunk < 3; chunk++) {
        const uint32_t* xc = g_xhl + chunk * CH;

#pragma unroll 1
        for (int kt = 0; kt < 8; kt++) {
            uint32_t ah[2][4], al[2][4];
#pragma unroll
            for (int j = 0; j < 2; j++) {
                int2 off = kof[kt * 8 + c4 + 4 * j];
#pragma unroll
                for (int mi = 0; mi < 2; mi++) {
                    uint32_t a0 = __ldg(xc + pbase[mi][0] + off.x);
                    uint32_t b0 = __ldg(xc + pbase[mi][0] + off.y);
                    uint32_t a1 = __ldg(xc + pbase[mi][1] + off.x);
                    uint32_t b1v = __ldg(xc + pbase[mi][1] + off.y);
                    ah[mi][2 * j]     = prmt(a0, b0, 0x7632u);
                    al[mi][2 * j]     = prmt(a0, b0, 0x5410u);
                    ah[mi][2 * j + 1] = prmt(a1, b1v, 0x7632u);
                    al[mi][2 * j + 1] = prmt(a1, b1v, 0x5410u);
                }
            }
            const uint4* bp = g_B1f + ((chunk * 8 + kt) * 16) * 32 + lane;
#pragma unroll
            for (int ni = 0; ni < 16; ni++) {
                uint4 bb = __ldg(bp + ni * 32);
                MMA(d1[0][ni], ah[0], bb.x, bb.y);
                MMA(d1[1][ni], ah[1], bb.x, bb.y);
                MMA(d1[0][ni], ah[0], bb.z, bb.w);
                MMA(d1[1][ni], ah[1], bb.z, bb.w);
                MMA(d1[0][ni], al[0], bb.x, bb.y);
                MMA(d1[1][ni], al[1], bb.x, bb.y);
            }
        }
    }

    // ============ layer 2: bias+leaky+split in regs, mma 128->64 ===========
    float4 d2[2][8];
#pragma unroll
    for (int mi = 0; mi < 2; mi++)
#pragma unroll
        for (int ni = 0; ni < 8; ni++) d2[mi][ni] = make_float4(0.f, 0.f, 0.f, 0.f);

#pragma unroll
    for (int kt = 0; kt < 8; kt++) {
        uint32_t ah[2][4], al[2][4];
#pragma unroll
        for (int half = 0; half < 2; half++) {
            int ni = 2 * kt + half;
            float2 bb = *(const float2*)&sb1[8 * ni + 2 * c4];
#pragma unroll
            for (int mi = 0; mi < 2; mi++) {
                float4 D = d1[mi][ni];
                float v0 = lrelu(D.x + bb.x);
                float v1 = lrelu(D.y + bb.y);
                float v2 = lrelu(D.z + bb.x);
                float v3 = lrelu(D.w + bb.y);
                split2(v0, v1, ah[mi][half * 2], al[mi][half * 2]);
                split2(v2, v3, ah[mi][half * 2 + 1], al[mi][half * 2 + 1]);
            }
        }
        const uint4* wp = g_W2f + (kt * 8) * 32 + lane;
#pragma unroll
        for (int ni = 0; ni < 8; ni++) {
            uint4 ww = __ldg(wp + ni * 32);
            MMA(d2[0][ni], ah[0], ww.x, ww.y);
            MMA(d2[1][ni], ah[1], ww.x, ww.y);
            MMA(d2[0][ni], ah[0], ww.z, ww.w);
            MMA(d2[1][ni], ah[1], ww.z, ww.w);
            MMA(d2[0][ni], al[0], ww.x, ww.y);
            MMA(d2[1][ni], al[1], ww.x, ww.y);
        }
    }

    // ============ h2 -> padded smem, per-pixel 64->8 + normalize ===========
    float* h2s = (float*)(smem + OFF_H2S) + w * (32 * 65);
#pragma unroll
    for (int ni = 0; ni < 8; ni++) {
        float2 bb = *(const float2*)&sb2[8 * ni + 2 * c4];
        int ch = 8 * ni + 2 * c4;
#pragma unroll
        for (int mi = 0; mi < 2; mi++) {
            float4 D = d2[mi][ni];
            int r0 = 16 * mi + g;
            h2s[r0 * 65 + ch]           = lrelu(D.x + bb.x);
            h2s[r0 * 65 + ch + 1]       = lrelu(D.y + bb.y);
            h2s[(r0 + 8) * 65 + ch]     = lrelu(D.z + bb.x);
            h2s[(r0 + 8) * 65 + ch + 1] = lrelu(D.w + bb.y);
        }
    }
    __syncwarp();

    const float* myrow = h2s + lane * 65;
    float v[F3];
#pragma unroll
    for (int e = 0; e < F3; e++) v[e] = sb3[e];
#pragma unroll 8
    for (int k = 0; k < F2; k++) {
        float hk = myrow[k];
        const float4* wr = (const float4*)&sW3[k * F3];
        float4 w0 = wr[0], w1 = wr[1];
        v[0] += hk * w0.x; v[1] += hk * w0.y; v[2] += hk * w0.z; v[3] += hk * w0.w;
        v[4] += hk * w1.x; v[5] += hk * w1.y; v[6] += hk * w1.z; v[7] += hk * w1.w;
    }
    float ss = 0.f;
#pragma unroll
    for (int e = 0; e < F3; e++) ss += v[e] * v[e];
    float inv = 1.0f / fmaxf(sqrtf(ss), 1e-12f);

    const int p = blockIdx.x * 128 + w * 32 + lane;
    float4* o = (float4*)(out + (size_t)p * F3);
    float4 o0, o1;
    o0.x = v[0] * inv; o0.y = v[1] * inv; o0.z = v[2] * inv; o0.w = v[3] * inv;
    o1.x = v[4] * inv; o1.y = v[5] * inv; o1.z = v[6] * inv; o1.w = v[7] * inv;
    o[0] = o0; o[1] = o1;
}

// ---------------------------------------------------------------------------
extern "C" void kernel_launch(void* const* d_in, const int* in_sizes, int n_in,
                              void* d_out, int out_size)
{
    const float* x  = (const float*)d_in[0];
    const float* W1 = (const float*)d_in[1];
    const float* b1 = (const float*)d_in[2];
    const float* W2 = (const float*)d_in[3];
    const float* b2 = (const float*)d_in[4];
    const float* W3 = (const float*)d_in[5];
    const float* b3 = (const float*)d_in[6];
    float* out = (float*)d_out;

    pad_k<<<(3 * CH + 255) / 256, 256>>>(x);
    prep_k<<<(12288 + 2048 + 255) / 256, 256>>>(W1, W2);

    cudaFuncSetAttribute(main_k, cudaFuncAttributeMaxDynamicSharedMemorySize,
                         SMEM_BYTES);
    main_k<<<NPIX / 128, 128, SMEM_BYTES>>>(b1, b2, b3, W3, out);
}

// round 11
// speedup vs baseline: 1.3305x; 1.2187x over previous
#include <cuda_runtime.h>
#include <cuda_fp16.h>
#include <cstdint>

#define IH 400
#define IW 400
#define NPIX 160000
#define F1 128
#define F2 64
#define F3 8

#define PW 416                 // padded image stride / height
#define CH (PW * PW)           // per-channel padded elems

// smem: h2 staging + small tables
#define OFF_H2S 0              // 4 warps x 32 px x 65 f32 = 33280 B
#define OFF_B1S 33280
#define OFF_B2S 33792
#define OFF_B3S 34048
#define OFF_W3S 34080
#define OFF_KOF 36128          // 64 x int2 = 512 B
#define SMEM_BYTES 36640

// padded input image, hi/lo fp16 packed per pixel: (hi<<16)|lo, zero border
__device__ uint32_t g_xhl[3 * CH];
// Pre-packed fp16 weight fragments (uint2 = {b0,b1} per lane, single precision pass)
__device__ uint2 g_B1f[3 * 4096];          // [chunk][kt][ni][lane]
__device__ uint2 g_W2f[2048];              // [kt][ni2][lane]

// ---------------- helpers ----------------
// pack two f32 -> f16x2 (upper = hi_val, lower = lo_val)
__device__ __forceinline__ uint32_t cvt2h(float hi_val, float lo_val) {
    uint32_t r;
    asm("cvt.rn.f16x2.f32 %0, %1, %2;" : "=r"(r) : "f"(hi_val), "f"(lo_val));
    return r;
}
// split (v0,v1) into hi f16x2 + exact-residual f16x2 (low half = v0)
__device__ __forceinline__ void split2h(float v0, float v1, uint32_t& h, uint32_t& l) {
    h = cvt2h(v1, v0);
    float f1 = __half2float(__ushort_as_half((unsigned short)(h >> 16)));
    float f0 = __half2float(__ushort_as_half((unsigned short)(h & 0xFFFFu)));
    l = cvt2h(v1 - f1, v0 - f0);
}
__device__ __forceinline__ uint32_t prmt(uint32_t a, uint32_t b, uint32_t s) {
    uint32_t r;
    asm("prmt.b32 %0, %1, %2, %3;" : "=r"(r) : "r"(a), "r"(b), "r"(s));
    return r;
}
__device__ __forceinline__ float lrelu(float t) { return t > 0.f ? t : 0.01f * t; }

#define MMA(d, a, b0_, b1_) \
    asm("mma.sync.aligned.m16n8k16.row.col.f32.f16.f16.f32 " \
        "{%0,%1,%2,%3},{%4,%5,%6,%7},{%8,%9},{%0,%1,%2,%3};" \
        : "+f"((d).x), "+f"((d).y), "+f"((d).z), "+f"((d).w) \
        : "r"((a)[0]), "r"((a)[1]), "r"((a)[2]), "r"((a)[3]), "r"(b0_), "r"(b1_))

// ---------------------------------------------------------------------------
// Prep 1: pad x into g_xhl (zero border, +5 offset), packed fp16 hi/lo
// ---------------------------------------------------------------------------
__global__ void pad_k(const float* __restrict__ x) {
    int i = blockIdx.x * 256 + threadIdx.x;
    if (i >= 3 * CH) return;
    int c = i / CH, rem = i - c * CH;
    int gy = rem / PW, gx = rem - gy * PW;
    uint32_t word = 0;
    int sy = gy - 5, sx = gx - 5;
    if ((unsigned)sy < (unsigned)IH && (unsigned)sx < (unsigned)IW) {
        float v = x[(c * IH + sy) * IW + sx];
        __half hv = __float2half_rn(v);
        __half lv = __float2half_rn(v - __half2float(hv));
        word = ((uint32_t)__half_as_ushort(hv) << 16) | __half_as_ushort(lv);
    }
    g_xhl[i] = word;
}

// ---------------------------------------------------------------------------
// Prep 2: pack W1 (363x128) and W2 (128x64) into mma.sync b-fragment layout,
// single fp16 per weight, zero-padded K.
// ---------------------------------------------------------------------------
__global__ void prep_k(const float* __restrict__ W1, const float* __restrict__ W2) {
    int t = blockIdx.x * 256 + threadIdx.x;
    if (t >= 12288 + 2048) return;
    if (t < 12288) {
        int lane = t & 31, ni = (t >> 5) & 15, kt = (t >> 9) & 7, chunk = t >> 12;
        int c = lane & 3, g = lane >> 2;
        int n = ni * 8 + g;
        int k0 = kt * 16 + 2 * c;
        float v00 = 0.f, v01 = 0.f, v10 = 0.f, v11 = 0.f;
        if (k0 + 1 < 121) {
            v00 = W1[(chunk * 121 + k0) * F1 + n];
            v01 = W1[(chunk * 121 + k0 + 1) * F1 + n];
        } else if (k0 < 121) {
            v00 = W1[(chunk * 121 + k0) * F1 + n];
        }
        if (k0 + 9 < 121) {
            v10 = W1[(chunk * 121 + k0 + 8) * F1 + n];
            v11 = W1[(chunk * 121 + k0 + 9) * F1 + n];
        } else if (k0 + 8 < 121) {
            v10 = W1[(chunk * 121 + k0 + 8) * F1 + n];
        }
        uint2 o;
        o.x = cvt2h(v01, v00);
        o.y = cvt2h(v11, v10);
        g_B1f[t] = o;
    } else {
        int t2 = t - 12288;
        int lane = t2 & 31, ni2 = (t2 >> 5) & 7, kt = t2 >> 8;
        int c = lane & 3, g = lane >> 2;
        int n = ni2 * 8 + g;
        int k0 = kt * 16 + 2 * c;
        uint2 o;
        o.x = cvt2h(W2[(k0 + 1) * F2 + n], W2[k0 * F2 + n]);
        o.y = cvt2h(W2[(k0 + 9) * F2 + n], W2[(k0 + 8) * F2 + n]);
        g_W2f[t2] = o;
    }
}

// ---------------------------------------------------------------------------
// Main: CTA = 128 px, 4 warps x 32 px. fp16 split-2: x = xh + xl exactly,
// weights single fp16 -> 2 MMAs per (ni, mi) k-step instead of 3.
// A fragments via PRMT from the pre-split packed image; B via LDG (L1/L2).
// ---------------------------------------------------------------------------
__global__ void __launch_bounds__(128) main_k(const float* __restrict__ b1,
                                              const float* __restrict__ b2,
                                              const float* __restrict__ b3,
                                              const float* __restrict__ W3,
                                              float* __restrict__ out)
{
    extern __shared__ char smem[];
    float* sb1 = (float*)(smem + OFF_B1S);
    float* sb2 = (float*)(smem + OFF_B2S);
    float* sb3 = (float*)(smem + OFF_B3S);
    float* sW3 = (float*)(smem + OFF_W3S);
    int2*  kof = (int2*)(smem + OFF_KOF);

    const int tid = threadIdx.x;
    const int w = tid >> 5;
    const int lane = tid & 31;
    const int c4 = lane & 3, g = lane >> 2;

    if (tid < F1) sb1[tid] = b1[tid];
    if (tid < F2) sb2[tid] = b2[tid];
    if (tid < F3) sb3[tid] = b3[tid];
    for (int i = tid; i < F2 * F3; i += 128) sW3[i] = W3[i];
    if (tid < 64) {                       // k -> padded-image offset table
        int k0 = 2 * tid, k1 = 2 * tid + 1;
        kof[tid] = make_int2((k0 / 11) * PW + (k0 % 11),
                             (k1 / 11) * PW + (k1 % 11));
    }
    __syncthreads();   // only block-wide sync

    // 4 pixel base offsets for this lane: rows g, g+8 in mi=0 / mi=1 tiles
    int pbase[2][2];
#pragma unroll
    for (int mi = 0; mi < 2; mi++)
#pragma unroll
        for (int rr = 0; rr < 2; rr++) {
            int p = blockIdx.x * 128 + w * 32 + mi * 16 + rr * 8 + g;
            int py = p / IW;
            pbase[mi][rr] = py * PW + (p - py * IW);
        }

    float4 d1[2][16];
#pragma unroll
    for (int mi = 0; mi < 2; mi++)
#pragma unroll
        for (int ni = 0; ni < 16; ni++) d1[mi][ni] = make_float4(0.f, 0.f, 0.f, 0.f);

    // ================= layer 1: K = 3 chunks x 128 (121 valid) =============
#pragma unroll 1
    for (int chunk = 0; chunk < 3; chunk++) {
        const uint32_t* xc = g_xhl + chunk * CH;

#pragma unroll 1
        for (int kt = 0; kt < 8; kt++) {
            uint32_t ah[2][4], al[2][4];
#pragma unroll
            for (int j = 0; j < 2; j++) {
                int2 off = kof[kt * 8 + c4 + 4 * j];
#pragma unroll
                for (int mi = 0; mi < 2; mi++) {
                    uint32_t a0 = __ldg(xc + pbase[mi][0] + off.x);
                    uint32_t b0 = __ldg(xc + pbase[mi][0] + off.y);
                    uint32_t a1 = __ldg(xc + pbase[mi][1] + off.x);
                    uint32_t b1v = __ldg(xc + pbase[mi][1] + off.y);
                    ah[mi][2 * j]     = prmt(a0, b0, 0x7632u);
                    al[mi][2 * j]     = prmt(a0, b0, 0x5410u);
                    ah[mi][2 * j + 1] = prmt(a1, b1v, 0x7632u);
                    al[mi][2 * j + 1] = prmt(a1, b1v, 0x5410u);
                }
            }
            const uint2* bp = g_B1f + ((chunk * 8 + kt) * 16) * 32 + lane;
#pragma unroll
            for (int ni = 0; ni < 16; ni++) {
                uint2 bb = __ldg(bp + ni * 32);
                MMA(d1[0][ni], ah[0], bb.x, bb.y);
                MMA(d1[1][ni], ah[1], bb.x, bb.y);
                MMA(d1[0][ni], al[0], bb.x, bb.y);
                MMA(d1[1][ni], al[1], bb.x, bb.y);
            }
        }
    }

    // ============ layer 2: bias+leaky+split in regs, mma 128->64 ===========
    float4 d2[2][8];
#pragma unroll
    for (int mi = 0; mi < 2; mi++)
#pragma unroll
        for (int ni = 0; ni < 8; ni++) d2[mi][ni] = make_float4(0.f, 0.f, 0.f, 0.f);

#pragma unroll
    for (int kt = 0; kt < 8; kt++) {
        uint32_t ah[2][4], al[2][4];
#pragma unroll
        for (int half = 0; half < 2; half++) {
            int ni = 2 * kt + half;
            float2 bb = *(const float2*)&sb1[8 * ni + 2 * c4];
#pragma unroll
            for (int mi = 0; mi < 2; mi++) {
                float4 D = d1[mi][ni];
                float v0 = lrelu(D.x + bb.x);
                float v1 = lrelu(D.y + bb.y);
                float v2 = lrelu(D.z + bb.x);
                float v3 = lrelu(D.w + bb.y);
                split2h(v0, v1, ah[mi][half * 2], al[mi][half * 2]);
                split2h(v2, v3, ah[mi][half * 2 + 1], al[mi][half * 2 + 1]);
            }
        }
        const uint2* wp = g_W2f + (kt * 8) * 32 + lane;
#pragma unroll
        for (int ni = 0; ni < 8; ni++) {
            uint2 ww = __ldg(wp + ni * 32);
            MMA(d2[0][ni], ah[0], ww.x, ww.y);
            MMA(d2[1][ni], ah[1], ww.x, ww.y);
            MMA(d2[0][ni], al[0], ww.x, ww.y);
            MMA(d2[1][ni], al[1], ww.x, ww.y);
        }
    }

    // ============ h2 -> padded smem, per-pixel 64->8 + normalize ===========
    float* h2s = (float*)(smem + OFF_H2S) + w * (32 * 65);
#pragma unroll
    for (int ni = 0; ni < 8; ni++) {
        float2 bb = *(const float2*)&sb2[8 * ni + 2 * c4];
        int ch = 8 * ni + 2 * c4;
#pragma unroll
        for (int mi = 0; mi < 2; mi++) {
            float4 D = d2[mi][ni];
            int r0 = 16 * mi + g;
            h2s[r0 * 65 + ch]           = lrelu(D.x + bb.x);
            h2s[r0 * 65 + ch + 1]       = lrelu(D.y + bb.y);
            h2s[(r0 + 8) * 65 + ch]     = lrelu(D.z + bb.x);
            h2s[(r0 + 8) * 65 + ch + 1] = lrelu(D.w + bb.y);
        }
    }
    __syncwarp();

    const float* myrow = h2s + lane * 65;
    float v[F3];
#pragma unroll
    for (int e = 0; e < F3; e++) v[e] = sb3[e];
#pragma unroll 8
    for (int k = 0; k < F2; k++) {
        float hk = myrow[k];
        const float4* wr = (const float4*)&sW3[k * F3];
        float4 w0 = wr[0], w1 = wr[1];
        v[0] += hk * w0.x; v[1] += hk * w0.y; v[2] += hk * w0.z; v[3] += hk * w0.w;
        v[4] += hk * w1.x; v[5] += hk * w1.y; v[6] += hk * w1.z; v[7] += hk * w1.w;
    }
    float ss = 0.f;
#pragma unroll
    for (int e = 0; e < F3; e++) ss += v[e] * v[e];
    float inv = 1.0f / fmaxf(sqrtf(ss), 1e-12f);

    const int p = blockIdx.x * 128 + w * 32 + lane;
    float4* o = (float4*)(out + (size_t)p * F3);
    float4 o0, o1;
    o0.x = v[0] * inv; o0.y = v[1] * inv; o0.z = v[2] * inv; o0.w = v[3] * inv;
    o1.x = v[4] * inv; o1.y = v[5] * inv; o1.z = v[6] * inv; o1.w = v[7] * inv;
    o[0] = o0; o[1] = o1;
}

// ---------------------------------------------------------------------------
extern "C" void kernel_launch(void* const* d_in, const int* in_sizes, int n_in,
                              void* d_out, int out_size)
{
    const float* x  = (const float*)d_in[0];
    const float* W1 = (const float*)d_in[1];
    const float* b1 = (const float*)d_in[2];
    const float* W2 = (const float*)d_in[3];
    const float* b2 = (const float*)d_in[4];
    const float* W3 = (const float*)d_in[5];
    const float* b3 = (const float*)d_in[6];
    float* out = (float*)d_out;

    pad_k<<<(3 * CH + 255) / 256, 256>>>(x);
    prep_k<<<(12288 + 2048 + 255) / 256, 256>>>(W1, W2);

    cudaFuncSetAttribute(main_k, cudaFuncAttributeMaxDynamicSharedMemorySize,
                         SMEM_BYTES);
    main_k<<<NPIX / 128, 128, SMEM_BYTES>>>(b1, b2, b3, W3, out);
}

// round 12
// speedup vs baseline: 1.5043x; 1.1306x over previous
#include <cuda_runtime.h>
#include <cuda_fp16.h>
#include <cstdint>

#define IH 400
#define IW 400
#define NPIX 160000
#define F1 128
#define F2 64
#define F3 8

#define PW 416                 // padded image stride / height
#define CH (PW * PW)           // per-channel padded elems

// smem: h2 staging + small tables
#define OFF_H2S 0              // 4 warps x 32 px x 65 f32 = 33280 B
#define OFF_B1S 33280
#define OFF_B2S 33792
#define OFF_B3S 34048
#define OFF_W3S 34080
#define OFF_KOF 36128          // 64 x int2 = 512 B
#define SMEM_BYTES 36640

// padded input image, hi/lo fp16 packed per pixel: (hi<<16)|lo, zero border
__device__ uint32_t g_xhl[3 * CH];
// Pre-packed fp16 weight fragments (uint2 = {b0,b1} per lane)
__device__ uint2 g_B1f[3 * 4096];          // [t = chunk*8+kt][ni][lane]
__device__ uint2 g_W2f[2048];              // [kt][ni2][lane]

// ---------------- helpers ----------------
__device__ __forceinline__ uint32_t cvt2h(float hi_val, float lo_val) {
    uint32_t r;
    asm("cvt.rn.f16x2.f32 %0, %1, %2;" : "=r"(r) : "f"(hi_val), "f"(lo_val));
    return r;
}
// split (v0,v1) into hi f16x2 + exact-residual f16x2 (low half = v0)
__device__ __forceinline__ void split2h(float v0, float v1, uint32_t& h, uint32_t& l) {
    h = cvt2h(v1, v0);
    float f1 = __half2float(__ushort_as_half((unsigned short)(h >> 16)));
    float f0 = __half2float(__ushort_as_half((unsigned short)(h & 0xFFFFu)));
    l = cvt2h(v1 - f1, v0 - f0);
}
__device__ __forceinline__ uint32_t prmt(uint32_t a, uint32_t b, uint32_t s) {
    uint32_t r;
    asm("prmt.b32 %0, %1, %2, %3;" : "=r"(r) : "r"(a), "r"(b), "r"(s));
    return r;
}
__device__ __forceinline__ float lrelu(float t) { return t > 0.f ? t : 0.01f * t; }

#define MMA(d, a, b0_, b1_) \
    asm("mma.sync.aligned.m16n8k16.row.col.f32.f16.f16.f32 " \
        "{%0,%1,%2,%3},{%4,%5,%6,%7},{%8,%9},{%0,%1,%2,%3};" \
        : "+f"((d).x), "+f"((d).y), "+f"((d).z), "+f"((d).w) \
        : "r"((a)[0]), "r"((a)[1]), "r"((a)[2]), "r"((a)[3]), "r"(b0_), "r"(b1_))

// ---------------------------------------------------------------------------
// Prep 1: pad x into g_xhl, 4 px per thread (vectorized stores)
// ---------------------------------------------------------------------------
__global__ void pad_k(const float* __restrict__ x) {
    int i4 = blockIdx.x * 256 + threadIdx.x;
    if (i4 >= 3 * CH / 4) return;
    int i = i4 * 4;
    int c = i / CH, rem = i - c * CH;
    int gy = rem / PW, gx0 = rem - gy * PW;
    int sy = gy - 5;
    uint4 wv = make_uint4(0, 0, 0, 0);
    if ((unsigned)sy < (unsigned)IH) {
        const float* xr = x + (c * IH + sy) * IW;
        uint32_t* wp = (uint32_t*)&wv;
#pragma unroll
        for (int q = 0; q < 4; q++) {
            int sx = gx0 + q - 5;
            if ((unsigned)sx < (unsigned)IW) {
                float v = __ldg(xr + sx);
                __half hv = __float2half_rn(v);
                __half lv = __float2half_rn(v - __half2float(hv));
                wp[q] = ((uint32_t)__half_as_ushort(hv) << 16) | __half_as_ushort(lv);
            }
        }
    }
    *(uint4*)(g_xhl + i) = wv;
}

// ---------------------------------------------------------------------------
// Prep 2: pack W1 (363x128) and W2 (128x64) into mma.sync b-fragment layout,
// single fp16 per weight, zero-padded K.
// ---------------------------------------------------------------------------
__global__ void prep_k(const float* __restrict__ W1, const float* __restrict__ W2) {
    int t = blockIdx.x * 256 + threadIdx.x;
    if (t >= 12288 + 2048) return;
    if (t < 12288) {
        int lane = t & 31, ni = (t >> 5) & 15, kt = (t >> 9) & 7, chunk = t >> 12;
        int c = lane & 3, g = lane >> 2;
        int n = ni * 8 + g;
        int k0 = kt * 16 + 2 * c;
        float v00 = 0.f, v01 = 0.f, v10 = 0.f, v11 = 0.f;
        if (k0 + 1 < 121) {
            v00 = W1[(chunk * 121 + k0) * F1 + n];
            v01 = W1[(chunk * 121 + k0 + 1) * F1 + n];
        } else if (k0 < 121) {
            v00 = W1[(chunk * 121 + k0) * F1 + n];
        }
        if (k0 + 9 < 121) {
            v10 = W1[(chunk * 121 + k0 + 8) * F1 + n];
            v11 = W1[(chunk * 121 + k0 + 9) * F1 + n];
        } else if (k0 + 8 < 121) {
            v10 = W1[(chunk * 121 + k0 + 8) * F1 + n];
        }
        uint2 o;
        o.x = cvt2h(v01, v00);
        o.y = cvt2h(v11, v10);
        g_B1f[t] = o;
    } else {
        int t2 = t - 12288;
        int lane = t2 & 31, ni2 = (t2 >> 5) & 7, kt = t2 >> 8;
        int c = lane & 3, g = lane >> 2;
        int n = ni2 * 8 + g;
        int k0 = kt * 16 + 2 * c;
        uint2 o;
        o.x = cvt2h(W2[(k0 + 1) * F2 + n], W2[k0 * F2 + n]);
        o.y = cvt2h(W2[(k0 + 9) * F2 + n], W2[(k0 + 8) * F2 + n]);
        g_W2f[t2] = o;
    }
}

// ---------------------------------------------------------------------------
// Main: CTA = 128 px, 4 warps x 32 px. fp16 split-2 MMAs; x loads software-
// pipelined one (chunk,kt) iteration ahead so L2 latency hides under MMAs.
// ---------------------------------------------------------------------------
__global__ void __launch_bounds__(128) main_k(const float* __restrict__ b1,
                                              const float* __restrict__ b2,
                                              const float* __restrict__ b3,
                                              const float* __restrict__ W3,
                                              float* __restrict__ out)
{
    extern __shared__ char smem[];
    float* sb1 = (float*)(smem + OFF_B1S);
    float* sb2 = (float*)(smem + OFF_B2S);
    float* sb3 = (float*)(smem + OFF_B3S);
    float* sW3 = (float*)(smem + OFF_W3S);
    int2*  kof = (int2*)(smem + OFF_KOF);

    const int tid = threadIdx.x;
    const int w = tid >> 5;
    const int lane = tid & 31;
    const int c4 = lane & 3, g = lane >> 2;

    if (tid < F1) sb1[tid] = b1[tid];
    if (tid < F2) sb2[tid] = b2[tid];
    if (tid < F3) sb3[tid] = b3[tid];
    for (int i = tid; i < F2 * F3; i += 128) sW3[i] = W3[i];
    if (tid < 64) {                       // k -> padded-image offset table
        int k0 = 2 * tid, k1 = 2 * tid + 1;
        kof[tid] = make_int2((k0 / 11) * PW + (k0 % 11),
                             (k1 / 11) * PW + (k1 % 11));
    }
    __syncthreads();   // only block-wide sync

    // 4 pixel base offsets for this lane: rows g, g+8 in mi=0 / mi=1 tiles
    int pbase[2][2];
#pragma unroll
    for (int mi = 0; mi < 2; mi++)
#pragma unroll
        for (int rr = 0; rr < 2; rr++) {
            int p = blockIdx.x * 128 + w * 32 + mi * 16 + rr * 8 + g;
            int py = p / IW;
            pbase[mi][rr] = py * PW + (p - py * IW);
        }

    // x-load for flattened iteration t = chunk*8 + kt (16 u32 per lane)
    auto ldx16 = [&](int t, uint32_t xr[16]) {
        const uint32_t* xc = g_xhl + (t >> 3) * CH;
        int kt = t & 7;
#pragma unroll
        for (int j = 0; j < 2; j++) {
            int2 off = kof[(kt << 3) + c4 + 4 * j];
#pragma unroll
            for (int mi = 0; mi < 2; mi++) {
                xr[j * 8 + mi * 4 + 0] = __ldg(xc + pbase[mi][0] + off.x);
                xr[j * 8 + mi * 4 + 1] = __ldg(xc + pbase[mi][0] + off.y);
                xr[j * 8 + mi * 4 + 2] = __ldg(xc + pbase[mi][1] + off.x);
                xr[j * 8 + mi * 4 + 3] = __ldg(xc + pbase[mi][1] + off.y);
            }
        }
    };

    float4 d1[2][16];
#pragma unroll
    for (int mi = 0; mi < 2; mi++)
#pragma unroll
        for (int ni = 0; ni < 16; ni++) d1[mi][ni] = make_float4(0.f, 0.f, 0.f, 0.f);

    // ================= layer 1: 24 flattened (chunk,kt) iterations =========
    uint32_t xr[16];
    ldx16(0, xr);
#pragma unroll 1
    for (int t = 0; t < 24; t++) {
        // consume prefetched x into fragments
        uint32_t ah[2][4], al[2][4];
#pragma unroll
        for (int j = 0; j < 2; j++)
#pragma unroll
            for (int mi = 0; mi < 2; mi++) {
                uint32_t a0 = xr[j * 8 + mi * 4 + 0];
                uint32_t b0 = xr[j * 8 + mi * 4 + 1];
                uint32_t a1 = xr[j * 8 + mi * 4 + 2];
                uint32_t b1v = xr[j * 8 + mi * 4 + 3];
                ah[mi][2 * j]     = prmt(a0, b0, 0x7632u);
                al[mi][2 * j]     = prmt(a0, b0, 0x5410u);
                ah[mi][2 * j + 1] = prmt(a1, b1v, 0x7632u);
                al[mi][2 * j + 1] = prmt(a1, b1v, 0x5410u);
            }

        // prefetch next iteration's x (lands under the MMAs below)
        int tn = (t < 23) ? t + 1 : 0;
        ldx16(tn, xr);

        const uint2* bp = g_B1f + (t * 16) * 32 + lane;
#pragma unroll
        for (int ni = 0; ni < 16; ni++) {
            uint2 bb = __ldg(bp + ni * 32);
            MMA(d1[0][ni], ah[0], bb.x, bb.y);
            MMA(d1[1][ni], ah[1], bb.x, bb.y);
            MMA(d1[0][ni], al[0], bb.x, bb.y);
            MMA(d1[1][ni], al[1], bb.x, bb.y);
        }
    }

    // ============ layer 2: bias+leaky+split in regs, mma 128->64 ===========
    float4 d2[2][8];
#pragma unroll
    for (int mi = 0; mi < 2; mi++)
#pragma unroll
        for (int ni = 0; ni < 8; ni++) d2[mi][ni] = make_float4(0.f, 0.f, 0.f, 0.f);

#pragma unroll
    for (int kt = 0; kt < 8; kt++) {
        uint32_t ah[2][4], al[2][4];
#pragma unroll
        for (int half = 0; half < 2; half++) {
            int ni = 2 * kt + half;
            float2 bb = *(const float2*)&sb1[8 * ni + 2 * c4];
#pragma unroll
            for (int mi = 0; mi < 2; mi++) {
                float4 D = d1[mi][ni];
                float v0 = lrelu(D.x + bb.x);
                float v1 = lrelu(D.y + bb.y);
                float v2 = lrelu(D.z + bb.x);
                float v3 = lrelu(D.w + bb.y);
                split2h(v0, v1, ah[mi][half * 2], al[mi][half * 2]);
                split2h(v2, v3, ah[mi][half * 2 + 1], al[mi][half * 2 + 1]);
            }
        }
        const uint2* wp = g_W2f + (kt * 8) * 32 + lane;
#pragma unroll
        for (int ni = 0; ni < 8; ni++) {
            uint2 ww = __ldg(wp + ni * 32);
            MMA(d2[0][ni], ah[0], ww.x, ww.y);
            MMA(d2[1][ni], ah[1], ww.x, ww.y);
            MMA(d2[0][ni], al[0], ww.x, ww.y);
            MMA(d2[1][ni], al[1], ww.x, ww.y);
        }
    }

    // ============ h2 -> padded smem, per-pixel 64->8 + normalize ===========
    float* h2s = (float*)(smem + OFF_H2S) + w * (32 * 65);
#pragma unroll
    for (int ni = 0; ni < 8; ni++) {
        float2 bb = *(const float2*)&sb2[8 * ni + 2 * c4];
        int ch = 8 * ni + 2 * c4;
#pragma unroll
        for (int mi = 0; mi < 2; mi++) {
            float4 D = d2[mi][ni];
            int r0 = 16 * mi + g;
            h2s[r0 * 65 + ch]           = lrelu(D.x + bb.x);
            h2s[r0 * 65 + ch + 1]       = lrelu(D.y + bb.y);
            h2s[(r0 + 8) * 65 + ch]     = lrelu(D.z + bb.x);
            h2s[(r0 + 8) * 65 + ch + 1] = lrelu(D.w + bb.y);
        }
    }
    __syncwarp();

    const float* myrow = h2s + lane * 65;
    float v[F3];
#pragma unroll
    for (int e = 0; e < F3; e++) v[e] = sb3[e];
#pragma unroll 8
    for (int k = 0; k < F2; k++) {
        float hk = myrow[k];
        const float4* wr = (const float4*)&sW3[k * F3];
        float4 w0 = wr[0], w1 = wr[1];
        v[0] += hk * w0.x; v[1] += hk * w0.y; v[2] += hk * w0.z; v[3] += hk * w0.w;
        v[4] += hk * w1.x; v[5] += hk * w1.y; v[6] += hk * w1.z; v[7] += hk * w1.w;
    }
    float ss = 0.f;
#pragma unroll
    for (int e = 0; e < F3; e++) ss += v[e] * v[e];
    float inv = 1.0f / fmaxf(sqrtf(ss), 1e-12f);

    const int p = blockIdx.x * 128 + w * 32 + lane;
    float4* o = (float4*)(out + (size_t)p * F3);
    float4 o0, o1;
    o0.x = v[0] * inv; o0.y = v[1] * inv; o0.z = v[2] * inv; o0.w = v[3] * inv;
    o1.x = v[4] * inv; o1.y = v[5] * inv; o1.z = v[6] * inv; o1.w = v[7] * inv;
    o[0] = o0; o[1] = o1;
}

// ---------------------------------------------------------------------------
extern "C" void kernel_launch(void* const* d_in, const int* in_sizes, int n_in,
                              void* d_out, int out_size)
{
    const float* x  = (const float*)d_in[0];
    const float* W1 = (const float*)d_in[1];
    const float* b1 = (const float*)d_in[2];
    const float* W2 = (const float*)d_in[3];
    const float* b2 = (const float*)d_in[4];
    const float* W3 = (const float*)d_in[5];
    const float* b3 = (const float*)d_in[6];
    float* out = (float*)d_out;

    pad_k<<<(3 * CH / 4 + 255) / 256, 256>>>(x);
    prep_k<<<(12288 + 2048 + 255) / 256, 256>>>(W1, W2);

    cudaFuncSetAttribute(main_k, cudaFuncAttributeMaxDynamicSharedMemorySize,
                         SMEM_BYTES);
    main_k<<<NPIX / 128, 128, SMEM_BYTES>>>(b1, b2, b3, W3, out);
}